// round 2
// baseline (speedup 1.0000x reference)
#include <cuda_runtime.h>
#include <cuda_bf16.h>
#include <cstdint>
#include <cstddef>

#define DIN 1024
#define DOUT 1024

// ---------------- GEMM tiling ----------------
#define BM 128
#define BN 128
#define BK 64                 // 64 bf16 = 128B rows (SW128)
#define NSTAGE 3
#define KITERS (DIN / BK)     // 16
#define THREADS 256
#define A_BYTES (BM * 128)    // 16384
#define B_BYTES (BN * 128)    // 16384
#define STAGE_BYTES (A_BYTES + B_BYTES)        // 32768
#define SMEM_TOTAL (NSTAGE * STAGE_BYTES)      // 98304

// Scratch (allocation-free rule: __device__ globals)
__device__ __nv_bfloat16 g_xq[8u * 8192u * 1024u];
__device__ __nv_bfloat16 g_wq[(size_t)DOUT * DIN];

// ============================ fake-quant kernel ============================
// Exact replication of the reference MXFP quantizer (block=32, EMAX=8,
// 6-bit mantissa via m=64, round-half-away, clip +-448). Result exact in bf16.
__global__ void quant_kernel(const float* __restrict__ in,
                             __nv_bfloat16* __restrict__ out, int nblocks) {
    int b = blockIdx.x * blockDim.x + threadIdx.x;
    if (b >= nblocks) return;
    const float4* src = reinterpret_cast<const float4*>(in) + (size_t)b * 8;
    float v[32];
#pragma unroll
    for (int i = 0; i < 8; i++) {
        float4 t = src[i];
        v[4 * i + 0] = t.x; v[4 * i + 1] = t.y;
        v[4 * i + 2] = t.z; v[4 * i + 3] = t.w;
    }
    float amax = 0.f;
#pragma unroll
    for (int i = 0; i < 32; i++) amax = fmaxf(amax, fabsf(v[i]));

    int se;  // shared exponent: floor(log2(amax)) - 8, clamped to -127
    if (amax == 0.f) {
        se = -127;
    } else {
        int ex = (__float_as_int(amax) >> 23) & 0xFF;
        int fl = (ex != 0) ? (ex - 127) : ilogbf(amax);   // exact floor(log2)
        se = fl - 8;
        if (se < -127) se = -127;
    }
    float scale     = ldexpf(1.f, se);
    float inv_scale = ldexpf(1.f, -se);

    unsigned short us[32];
#pragma unroll
    for (int i = 0; i < 32; i++) {
        float vv = v[i] * inv_scale;       // exact power-of-2 scaling
        float av = fabsf(vv);
        float q;
        if (av == 0.f) {
            q = 0.f;
        } else {
            int pex = (__float_as_int(av) >> 23) & 0xFF;
            int pe  = pex - 127;           // exact floor(log2|v|) for normals
            if (pe < -6) pe = -6;          // (subnormals clamp here too)
            float stp = ldexpf(1.f, pe - 6);                    // pscale/64
            float r = floorf(av * ldexpf(1.f, 6 - pe) + 0.5f);  // round-half-away
            q = copysignf(r * stp, vv);
            q = fminf(fmaxf(q, -448.f), 448.f);
        }
        us[i] = __bfloat16_as_ushort(__float2bfloat16(q * scale));  // exact cast
    }
    uint4* dst = reinterpret_cast<uint4*>(out + (size_t)b * 32);
    const uint4* su = reinterpret_cast<const uint4*>(us);
#pragma unroll
    for (int i = 0; i < 4; i++) dst[i] = su[i];
}

// ============================ PTX helpers ============================
__device__ __forceinline__ uint32_t smem_u32(const void* p) {
    return (uint32_t)__cvta_generic_to_shared(p);
}
#define SW128(o) ((o) ^ (((o) >> 3) & 0x70))

__device__ __forceinline__ void cp16(uint32_t dst, const void* src) {
    asm volatile("cp.async.cg.shared.global [%0], [%1], 16;" :: "r"(dst), "l"(src));
}
__device__ __forceinline__ void ldsm4(uint32_t& r0, uint32_t& r1, uint32_t& r2,
                                      uint32_t& r3, uint32_t a) {
    asm volatile("ldmatrix.sync.aligned.m8n8.x4.shared.b16 {%0,%1,%2,%3}, [%4];"
                 : "=r"(r0), "=r"(r1), "=r"(r2), "=r"(r3) : "r"(a));
}
__device__ __forceinline__ void mma16816(float* c, const uint32_t* a,
                                         const uint32_t* b) {
    asm volatile(
        "mma.sync.aligned.m16n8k16.row.col.f32.bf16.bf16.f32 "
        "{%0,%1,%2,%3}, {%4,%5,%6,%7}, {%8,%9}, {%0,%1,%2,%3};"
        : "+f"(c[0]), "+f"(c[1]), "+f"(c[2]), "+f"(c[3])
        : "r"(a[0]), "r"(a[1]), "r"(a[2]), "r"(a[3]), "r"(b[0]), "r"(b[1]));
}

// ============================ GEMM kernel ============================
// A = xq [M, K] row-major (K contiguous), B = wq [N, K] row-major (K contiguous)
// out[m][n] = sum_k A[m][k]*B[n][k] + bias[n]
__global__ void __launch_bounds__(THREADS)
gemm_kernel(const __nv_bfloat16* __restrict__ A, const __nv_bfloat16* __restrict__ Bw,
            const float* __restrict__ bias, float* __restrict__ out) {
    extern __shared__ __align__(1024) char smem[];
    uint32_t sb = smem_u32(smem);
    int tid = threadIdx.x, wid = tid >> 5, lid = tid & 31;
    int n0 = blockIdx.x * BN;
    int m0 = blockIdx.y * BM;
    int wm = wid & 3;          // A row block (4 x 32)
    int wn = wid >> 2;         // B col block (2 x 64)

    // per-lane ldmatrix address components
    int laneA_row = (lid & 7) + ((lid >> 3) & 1) * 8;   // 0..15
    int laneA_koff = (lid >> 4) * 16;                   // 0 or 16 bytes
    int laneB_row = (lid & 7) + (lid >> 4) * 8;         // 0..15
    int laneB_koff = ((lid >> 3) & 1) * 16;             // 0 or 16 bytes

    float c[2][8][4];
#pragma unroll
    for (int t = 0; t < 2; t++)
#pragma unroll
        for (int i = 0; i < 8; i++)
#pragma unroll
            for (int j = 0; j < 4; j++) c[t][i][j] = 0.f;

    // ---- async load of one K-stage ----
    auto load_stage = [&](int buf, int kc) {
        uint32_t abase = sb + buf * STAGE_BYTES;
        uint32_t bbase = abase + A_BYTES;
        int k0 = kc * BK;
#pragma unroll
        for (int t = 0; t < 4; t++) {
            int idx = t * THREADS + tid;          // 1024 chunks of 16B
            int r = idx >> 3, j = idx & 7;
            cp16(abase + SW128(r * 128 + j * 16),
                 A + (size_t)(m0 + r) * DIN + k0 + j * 8);
        }
#pragma unroll
        for (int t = 0; t < 4; t++) {
            int idx = t * THREADS + tid;
            int r = idx >> 3, j = idx & 7;
            cp16(bbase + SW128(r * 128 + j * 16),
                 Bw + (size_t)(n0 + r) * DIN + k0 + j * 8);
        }
        asm volatile("cp.async.commit_group;" ::: "memory");
    };

    load_stage(0, 0);
    load_stage(1, 1);

    for (int i = 0; i < KITERS; i++) {
        int buf = i % NSTAGE;
        if (i < KITERS - 1)
            asm volatile("cp.async.wait_group 1;" ::: "memory");
        else
            asm volatile("cp.async.wait_group 0;" ::: "memory");
        __syncthreads();

        if (i + 2 < KITERS) load_stage((i + 2) % NSTAGE, i + 2);

        uint32_t aS = sb + buf * STAGE_BYTES;
        uint32_t bS = aS + A_BYTES;
#pragma unroll
        for (int kk = 0; kk < 4; kk++) {
            uint32_t afrag[2][4];
#pragma unroll
            for (int t = 0; t < 2; t++) {
                int row = wm * 32 + t * 16 + laneA_row;
                ldsm4(afrag[t][0], afrag[t][1], afrag[t][2], afrag[t][3],
                      aS + SW128(row * 128 + kk * 32 + laneA_koff));
            }
            uint32_t bfrag[8][2];
#pragma unroll
            for (int p = 0; p < 4; p++) {
                int row = wn * 64 + p * 16 + laneB_row;
                uint32_t r0, r1, r2, r3;
                ldsm4(r0, r1, r2, r3,
                      bS + SW128(row * 128 + kk * 32 + laneB_koff));
                bfrag[2 * p][0] = r0;     bfrag[2 * p][1] = r1;
                bfrag[2 * p + 1][0] = r2; bfrag[2 * p + 1][1] = r3;
            }
#pragma unroll
            for (int t = 0; t < 2; t++)
#pragma unroll
                for (int q = 0; q < 8; q++)
                    mma16816(c[t][q], afrag[t], bfrag[q]);
        }
    }

    // ---- epilogue: fused bias + float2 stores ----
    int ncol0 = n0 + wn * 64 + (lid & 3) * 2;
    float2 bb[8];
#pragma unroll
    for (int q = 0; q < 8; q++)
        bb[q] = *reinterpret_cast<const float2*>(bias + ncol0 + q * 8);

#pragma unroll
    for (int t = 0; t < 2; t++) {
#pragma unroll
        for (int h = 0; h < 2; h++) {
            int m = m0 + wm * 32 + t * 16 + h * 8 + (lid >> 2);
            float* orow = out + (size_t)m * DOUT;
#pragma unroll
            for (int q = 0; q < 8; q++) {
                float2 v;
                v.x = c[t][q][2 * h + 0] + bb[q].x;
                v.y = c[t][q][2 * h + 1] + bb[q].y;
                *reinterpret_cast<float2*>(orow + ncol0 + q * 8) = v;
            }
        }
    }
}

// ============================ launch ============================
extern "C" void kernel_launch(void* const* d_in, const int* in_sizes, int n_in,
                              void* d_out, int out_size) {
    const float* x    = (const float*)d_in[0];
    const float* w    = (const float*)d_in[1];
    const float* bias = (const float*)d_in[2];
    float* out = (float*)d_out;
    int M = in_sizes[0] / DIN;   // 65536

    __nv_bfloat16 *xq, *wq;
    cudaGetSymbolAddress((void**)&xq, g_xq);
    cudaGetSymbolAddress((void**)&wq, g_wq);

    int xblocks = (M * DIN) / 32;
    int wblocks = (DOUT * DIN) / 32;
    quant_kernel<<<(xblocks + 255) / 256, 256>>>(x, xq, xblocks);
    quant_kernel<<<(wblocks + 255) / 256, 256>>>(w, wq, wblocks);

    cudaFuncSetAttribute(gemm_kernel, cudaFuncAttributeMaxDynamicSharedMemorySize,
                         SMEM_TOTAL);
    dim3 grid(DOUT / BN, M / BM);   // (8, 512)
    gemm_kernel<<<grid, THREADS, SMEM_TOTAL>>>(xq, wq, bias, out);
}